// round 1
// baseline (speedup 1.0000x reference)
#include <cuda_runtime.h>
#include <cuda_bf16.h>
#include <math.h>

#define NTOK   1024
#define HID    768
#define FFN    3072
#define NEXP   8
#define TOPK   2
#define SLOTS  (NTOK * TOPK)
#define TILE_M 64
#define MAXROWS 2560              // 2048 + 8*63 rounded up to 64
#define MAX_MT (MAXROWS / TILE_M) // 40
#define NT1    (FFN / TILE_M)     // 48
#define NT2    (HID / TILE_M)     // 12

// ---------------- scratch (device globals; no allocations allowed) ----------
__device__ int   g_count[NEXP];
__device__ int   g_off[NEXP + 1];
__device__ int   g_tile_expert[MAX_MT];
__device__ int   g_slot_e[SLOTS];
__device__ int   g_slot_pos[SLOTS];
__device__ int   g_slot_row[SLOTS];
__device__ float g_slot_gate[SLOTS];
__device__ int   g_row_token[MAXROWS];
__device__ float g_H[MAXROWS * FFN]; // ~31.5 MB
__device__ float g_Y[MAXROWS * HID]; // ~7.9 MB

// ---------------- init: zero counts, invalidate rows ------------------------
__global__ void init_kernel() {
    int i = blockIdx.x * blockDim.x + threadIdx.x;
    if (i < MAXROWS) g_row_token[i] = -1;
    if (i < NEXP) g_count[i] = 0;
}

// ---------------- router: one warp per token --------------------------------
__global__ void router_kernel(const float* __restrict__ x,
                              const float* __restrict__ rw) {
    int gtid = blockIdx.x * blockDim.x + threadIdx.x;
    int tok  = gtid >> 5;
    int lane = gtid & 31;
    if (tok >= NTOK) return;

    const float* xp = x + tok * HID;
    float acc[NEXP];
#pragma unroll
    for (int e = 0; e < NEXP; e++) acc[e] = 0.f;

    for (int i = lane; i < HID; i += 32) {
        float xv = xp[i];
        const float* r = rw + i * NEXP;
#pragma unroll
        for (int e = 0; e < NEXP; e++) acc[e] += xv * r[e];
    }
#pragma unroll
    for (int off = 16; off; off >>= 1)
#pragma unroll
        for (int e = 0; e < NEXP; e++)
            acc[e] += __shfl_xor_sync(0xFFFFFFFFu, acc[e], off);

    if (lane == 0) {
        int i1 = 0; float v1 = acc[0];
#pragma unroll
        for (int e = 1; e < NEXP; e++)
            if (acc[e] > v1) { v1 = acc[e]; i1 = e; }
        int i2 = -1; float v2 = -INFINITY;
#pragma unroll
        for (int e = 0; e < NEXP; e++)
            if (e != i1 && acc[e] > v2) { v2 = acc[e]; i2 = e; }

        // renormalized top-2 gates == softmax over {v1, v2} (Z cancels)
        float g1 = 1.f / (1.f + expf(v2 - v1));
        float g2 = 1.f - g1;

        int s0 = tok * 2, s1 = s0 + 1;
        g_slot_e[s0] = i1; g_slot_gate[s0] = g1;
        g_slot_pos[s0] = atomicAdd(&g_count[i1], 1);
        g_slot_e[s1] = i2; g_slot_gate[s1] = g2;
        g_slot_pos[s1] = atomicAdd(&g_count[i2], 1);
    }
}

// ---------------- scan: padded per-expert offsets + tile->expert map --------
__global__ void scan_kernel() {
    if (threadIdx.x != 0 || blockIdx.x != 0) return;
    int off = 0;
    for (int e = 0; e < NEXP; e++) {
        g_off[e] = off;
        int pad = ((g_count[e] + TILE_M - 1) / TILE_M) * TILE_M;
        off += pad;
    }
    g_off[NEXP] = off;
    for (int t = 0; t < MAX_MT; t++) {
        int rbase = t * TILE_M;
        int ex = -1;
        for (int e = 0; e < NEXP; e++)
            if (rbase >= g_off[e] && rbase < g_off[e + 1]) { ex = e; break; }
        g_tile_expert[t] = ex;
    }
}

// ---------------- scatter: slot -> padded row -------------------------------
__global__ void scatter_kernel() {
    int s = blockIdx.x * blockDim.x + threadIdx.x;
    if (s >= SLOTS) return;
    int e   = g_slot_e[s];
    int row = g_off[e] + g_slot_pos[s];
    g_slot_row[s]   = row;
    g_row_token[row] = s >> 1;
}

// ---------------- GEMM1: H = gelu(X_gather @ W1[e]),  K=768 -----------------
__global__ void __launch_bounds__(256) ffn1_kernel(const float* __restrict__ x,
                                                   const float* __restrict__ w1) {
    int mt = blockIdx.x, nt = blockIdx.y;
    int e = g_tile_expert[mt];
    if (e < 0) return;

    __shared__ float As[TILE_M][17];   // [m][k], padded
    __shared__ float Bs[16][TILE_M];   // [k][n]

    int tid = threadIdx.x;
    int tx = tid & 15, ty = tid >> 4;  // 16x16
    int rbase = mt * TILE_M;
    const float* w1e = w1 + (size_t)e * HID * FFN;

    float c[4][4];
#pragma unroll
    for (int i = 0; i < 4; i++)
#pragma unroll
        for (int j = 0; j < 4; j++) c[i][j] = 0.f;

    // A-loader mapping: row = tid/4, 4 consecutive k's
    int arow = tid >> 2;
    int akq  = (tid & 3) * 4;
    int atok = g_row_token[rbase + arow];
    const float* arow_ptr = (atok >= 0) ? (x + (size_t)atok * HID) : nullptr;
    // B-loader mapping: k = tid/16, 4 consecutive n's
    int bk  = tid >> 4;
    int bnq = (tid & 15) * 4;

    for (int k0 = 0; k0 < HID; k0 += 16) {
        float4 av = make_float4(0.f, 0.f, 0.f, 0.f);
        if (arow_ptr) av = *(const float4*)(arow_ptr + k0 + akq);
        As[arow][akq + 0] = av.x;
        As[arow][akq + 1] = av.y;
        As[arow][akq + 2] = av.z;
        As[arow][akq + 3] = av.w;

        float4 bv = *(const float4*)(w1e + (size_t)(k0 + bk) * FFN + nt * TILE_M + bnq);
        *(float4*)&Bs[bk][bnq] = bv;

        __syncthreads();
#pragma unroll
        for (int k = 0; k < 16; k++) {
            float a0 = As[ty * 4 + 0][k];
            float a1 = As[ty * 4 + 1][k];
            float a2 = As[ty * 4 + 2][k];
            float a3 = As[ty * 4 + 3][k];
            float4 b = *(float4*)&Bs[k][tx * 4];
            c[0][0] += a0 * b.x; c[0][1] += a0 * b.y; c[0][2] += a0 * b.z; c[0][3] += a0 * b.w;
            c[1][0] += a1 * b.x; c[1][1] += a1 * b.y; c[1][2] += a1 * b.z; c[1][3] += a1 * b.w;
            c[2][0] += a2 * b.x; c[2][1] += a2 * b.y; c[2][2] += a2 * b.z; c[2][3] += a2 * b.w;
            c[3][0] += a3 * b.x; c[3][1] += a3 * b.y; c[3][2] += a3 * b.z; c[3][3] += a3 * b.w;
        }
        __syncthreads();
    }

#pragma unroll
    for (int i = 0; i < 4; i++) {
        int row = rbase + ty * 4 + i;
        float* hp = g_H + (size_t)row * FFN + nt * TILE_M + tx * 4;
#pragma unroll
        for (int j = 0; j < 4; j++) {
            float v = c[i][j];
            v = 0.5f * v * (1.f + erff(v * 0.70710678118654752f)); // exact gelu
            hp[j] = v;
        }
    }
}

// ---------------- GEMM2: Y = H @ W2[e],  K=3072 -----------------------------
__global__ void __launch_bounds__(256) ffn2_kernel(const float* __restrict__ w2) {
    int mt = blockIdx.x, nt = blockIdx.y;
    int e = g_tile_expert[mt];
    if (e < 0) return;

    __shared__ float As[TILE_M][17];
    __shared__ float Bs[16][TILE_M];

    int tid = threadIdx.x;
    int tx = tid & 15, ty = tid >> 4;
    int rbase = mt * TILE_M;
    const float* w2e = w2 + (size_t)e * FFN * HID;

    float c[4][4];
#pragma unroll
    for (int i = 0; i < 4; i++)
#pragma unroll
        for (int j = 0; j < 4; j++) c[i][j] = 0.f;

    int arow = tid >> 2;
    int akq  = (tid & 3) * 4;
    const float* arow_ptr = g_H + (size_t)(rbase + arow) * FFN;
    int bk  = tid >> 4;
    int bnq = (tid & 15) * 4;

    for (int k0 = 0; k0 < FFN; k0 += 16) {
        float4 av = *(const float4*)(arow_ptr + k0 + akq);
        As[arow][akq + 0] = av.x;
        As[arow][akq + 1] = av.y;
        As[arow][akq + 2] = av.z;
        As[arow][akq + 3] = av.w;

        float4 bv = *(const float4*)(w2e + (size_t)(k0 + bk) * HID + nt * TILE_M + bnq);
        *(float4*)&Bs[bk][bnq] = bv;

        __syncthreads();
#pragma unroll
        for (int k = 0; k < 16; k++) {
            float a0 = As[ty * 4 + 0][k];
            float a1 = As[ty * 4 + 1][k];
            float a2 = As[ty * 4 + 2][k];
            float a3 = As[ty * 4 + 3][k];
            float4 b = *(float4*)&Bs[k][tx * 4];
            c[0][0] += a0 * b.x; c[0][1] += a0 * b.y; c[0][2] += a0 * b.z; c[0][3] += a0 * b.w;
            c[1][0] += a1 * b.x; c[1][1] += a1 * b.y; c[1][2] += a1 * b.z; c[1][3] += a1 * b.w;
            c[2][0] += a2 * b.x; c[2][1] += a2 * b.y; c[2][2] += a2 * b.z; c[2][3] += a2 * b.w;
            c[3][0] += a3 * b.x; c[3][1] += a3 * b.y; c[3][2] += a3 * b.z; c[3][3] += a3 * b.w;
        }
        __syncthreads();
    }

#pragma unroll
    for (int i = 0; i < 4; i++) {
        int row = rbase + ty * 4 + i;
        float* yp = g_Y + (size_t)row * HID + nt * TILE_M + tx * 4;
#pragma unroll
        for (int j = 0; j < 4; j++) yp[j] = c[i][j];
    }
}

// ---------------- combine: out[n] = g0*Y[r0] + g1*Y[r1] ---------------------
__global__ void combine_kernel(float* __restrict__ out) {
    int n = blockIdx.x;
    int h4 = threadIdx.x * 4;
    if (h4 >= HID) return;
    int   r0 = g_slot_row[2 * n],     r1 = g_slot_row[2 * n + 1];
    float g0 = g_slot_gate[2 * n],    g1 = g_slot_gate[2 * n + 1];
    float4 a = *(const float4*)(g_Y + (size_t)r0 * HID + h4);
    float4 b = *(const float4*)(g_Y + (size_t)r1 * HID + h4);
    float4 o;
    o.x = g0 * a.x + g1 * b.x;
    o.y = g0 * a.y + g1 * b.y;
    o.z = g0 * a.z + g1 * b.z;
    o.w = g0 * a.w + g1 * b.w;
    *(float4*)(out + (size_t)n * HID + h4) = o;
}

// ---------------- launch -----------------------------------------------------
extern "C" void kernel_launch(void* const* d_in, const int* in_sizes, int n_in,
                              void* d_out, int out_size) {
    const float* x  = (const float*)d_in[0];
    const float* rw = (const float*)d_in[1];
    const float* w1 = (const float*)d_in[2];
    const float* w2 = (const float*)d_in[3];
    float* out = (float*)d_out;

    init_kernel<<<(MAXROWS + 255) / 256, 256>>>();
    router_kernel<<<(NTOK * 32 + 255) / 256, 256>>>(x, rw);
    scan_kernel<<<1, 32>>>();
    scatter_kernel<<<(SLOTS + 255) / 256, 256>>>();
    ffn1_kernel<<<dim3(MAX_MT, NT1), 256>>>(x, w1);
    ffn2_kernel<<<dim3(MAX_MT, NT2), 256>>>(w2);
    combine_kernel<<<NTOK, HID / 4>>>(out);
}

// round 3
// speedup vs baseline: 2.6394x; 2.6394x over previous
#include <cuda_runtime.h>
#include <cuda_bf16.h>
#include <math.h>
#include <stdint.h>

#define NTOK   1024
#define HID    768
#define FFN    3072
#define NEXP   8
#define SLOTS  (NTOK * 2)
#define TILE_M 128
#define TILE_N 128
#define TILE_K 64
#define MAXROWS 3072
#define MAX_MT (MAXROWS / TILE_M)   // 24
#define NT1    (FFN / TILE_N)       // 24
#define NT2    (HID / TILE_N)       // 6

// SMEM per buffer: Ah 16K | Al 16K | Bh 16K | Bl 16K = 64KB; 2 buffers
#define OFF_AH  0
#define OFF_AL  16384
#define OFF_BH  32768
#define OFF_BL  49152
#define BUF_STRIDE 65536
#define SMEM_BYTES (2 * BUF_STRIDE)

// ---------------- scratch ----------------------------------------------------
__device__ int   g_count[NEXP];
__device__ int   g_off[NEXP + 1];
__device__ int   g_tile_expert[MAX_MT];
__device__ int   g_slot_e[SLOTS];
__device__ int   g_slot_pos[SLOTS];
__device__ int   g_slot_row[SLOTS];
__device__ float g_slot_gate[SLOTS];
__device__ int   g_row_token[MAXROWS];
__device__ __nv_bfloat16 g_Hh[(size_t)MAXROWS * FFN];
__device__ __nv_bfloat16 g_Hl[(size_t)MAXROWS * FFN];
__device__ float g_Y[(size_t)MAXROWS * HID];

// ---------------- helpers ----------------------------------------------------
__device__ __forceinline__ uint32_t smem_u32(const void* p) {
    uint32_t a;
    asm("{ .reg .u64 t; cvta.to.shared.u64 t, %1; cvt.u32.u64 %0, t; }" : "=r"(a) : "l"(p));
    return a;
}
__device__ __forceinline__ void ldsm_x4(uint32_t* r, uint32_t addr) {
    asm volatile("ldmatrix.sync.aligned.m8n8.x4.shared.b16 {%0,%1,%2,%3}, [%4];"
        : "=r"(r[0]), "=r"(r[1]), "=r"(r[2]), "=r"(r[3]) : "r"(addr));
}
__device__ __forceinline__ void ldsm_x4_t(uint32_t* r, uint32_t addr) {
    asm volatile("ldmatrix.sync.aligned.m8n8.x4.trans.shared.b16 {%0,%1,%2,%3}, [%4];"
        : "=r"(r[0]), "=r"(r[1]), "=r"(r[2]), "=r"(r[3]) : "r"(addr));
}
__device__ __forceinline__ void mma_bf16(float* c, const uint32_t* a, uint32_t b0, uint32_t b1) {
    asm volatile("mma.sync.aligned.m16n8k16.row.col.f32.bf16.bf16.f32 "
        "{%0,%1,%2,%3}, {%4,%5,%6,%7}, {%8,%9}, {%0,%1,%2,%3};"
        : "+f"(c[0]), "+f"(c[1]), "+f"(c[2]), "+f"(c[3])
        : "r"(a[0]), "r"(a[1]), "r"(a[2]), "r"(a[3]), "r"(b0), "r"(b1));
}
__device__ __forceinline__ uint32_t pack_hi2(float f0, float f1) {
    __nv_bfloat162 h = __floats2bfloat162_rn(f0, f1);
    return *reinterpret_cast<uint32_t*>(&h);
}
__device__ __forceinline__ uint32_t pack_lo2(float f0, float f1, uint32_t hibits) {
    __nv_bfloat162 h = *reinterpret_cast<__nv_bfloat162*>(&hibits);
    float r0 = f0 - __bfloat162float(h.x);
    float r1 = f1 - __bfloat162float(h.y);
    __nv_bfloat162 l = __floats2bfloat162_rn(r0, r1);
    return *reinterpret_cast<uint32_t*>(&l);
}
__device__ __forceinline__ float gelu_ex(float v) {
    return 0.5f * v * (1.f + erff(v * 0.70710678118654752f));
}
// swizzles: A [m][k] 128B rows; B [k][n] 256B rows
__device__ __forceinline__ uint32_t swA(uint32_t m, uint32_t kbyte) {
    return (m * 128 + kbyte) ^ ((m & 7) << 4);
}
__device__ __forceinline__ uint32_t swB(uint32_t k, uint32_t nbyte) {
    return (k * 256 + nbyte) ^ ((k & 7) << 4);
}

// ---------------- init / router / scan / scatter -----------------------------
__global__ void init_kernel() {
    int i = blockIdx.x * blockDim.x + threadIdx.x;
    if (i < MAXROWS) g_row_token[i] = -1;
    if (i < NEXP) g_count[i] = 0;
}

__global__ void router_kernel(const float* __restrict__ x,
                              const float* __restrict__ rw) {
    int gtid = blockIdx.x * blockDim.x + threadIdx.x;
    int tok  = gtid >> 5;
    int lane = gtid & 31;
    if (tok >= NTOK) return;
    const float* xp = x + tok * HID;
    float acc[NEXP];
#pragma unroll
    for (int e = 0; e < NEXP; e++) acc[e] = 0.f;
    for (int i = lane; i < HID; i += 32) {
        float xv = xp[i];
        const float* r = rw + i * NEXP;
#pragma unroll
        for (int e = 0; e < NEXP; e++) acc[e] += xv * r[e];
    }
#pragma unroll
    for (int off = 16; off; off >>= 1)
#pragma unroll
        for (int e = 0; e < NEXP; e++)
            acc[e] += __shfl_xor_sync(0xFFFFFFFFu, acc[e], off);
    if (lane == 0) {
        int i1 = 0; float v1 = acc[0];
#pragma unroll
        for (int e = 1; e < NEXP; e++)
            if (acc[e] > v1) { v1 = acc[e]; i1 = e; }
        int i2 = -1; float v2 = -INFINITY;
#pragma unroll
        for (int e = 0; e < NEXP; e++)
            if (e != i1 && acc[e] > v2) { v2 = acc[e]; i2 = e; }
        float g1 = 1.f / (1.f + expf(v2 - v1));
        float g2 = 1.f - g1;
        int s0 = tok * 2, s1 = s0 + 1;
        g_slot_e[s0] = i1; g_slot_gate[s0] = g1;
        g_slot_pos[s0] = atomicAdd(&g_count[i1], 1);
        g_slot_e[s1] = i2; g_slot_gate[s1] = g2;
        g_slot_pos[s1] = atomicAdd(&g_count[i2], 1);
    }
}

__global__ void scan_kernel() {
    if (threadIdx.x != 0 || blockIdx.x != 0) return;
    int off = 0;
    for (int e = 0; e < NEXP; e++) {
        g_off[e] = off;
        off += ((g_count[e] + TILE_M - 1) / TILE_M) * TILE_M;
    }
    g_off[NEXP] = off;
    for (int t = 0; t < MAX_MT; t++) {
        int rbase = t * TILE_M;
        int ex = -1;
        for (int e = 0; e < NEXP; e++)
            if (rbase >= g_off[e] && rbase < g_off[e + 1]) { ex = e; break; }
        g_tile_expert[t] = ex;
    }
}

__global__ void scatter_kernel() {
    int s = blockIdx.x * blockDim.x + threadIdx.x;
    if (s >= SLOTS) return;
    int e   = g_slot_e[s];
    int row = g_off[e] + g_slot_pos[s];
    g_slot_row[s]    = row;
    g_row_token[row] = s >> 1;
}

// ---------------- shared compute: 8 warps, warp tile 64x32 -------------------
// acc[mi][nj][4], mi 0..3 (16-row tiles), nj 0..3 (8-col tiles)
__device__ __forceinline__ void compute_chunk(uint32_t b32, int wm, int wn, int lane,
                                              float acc[4][4][4]) {
    uint32_t aAh = b32 + OFF_AH, aAl = b32 + OFF_AL;
    uint32_t aBh = b32 + OFF_BH, aBl = b32 + OFF_BL;
    // lane mapping for LDSM
    uint32_t a_row = wm * 64 + (lane & 15);
    uint32_t a_kc  = (lane >> 4) * 16;            // bytes: *8 elems *2B
    uint32_t b_k   = (lane & 7) + ((lane >> 3) & 1) * 8;
    uint32_t b_nc  = (lane >> 4) * 16;            // bytes
#pragma unroll
    for (int ks = 0; ks < 4; ks++) {
        uint32_t k0 = ks * 16;
        uint32_t ah[4][4], al[4][4], bh[2][4], bl[2][4];
#pragma unroll
        for (int mi = 0; mi < 4; mi++) {
            uint32_t addr = swA(a_row + mi * 16, k0 * 2 + a_kc);
            ldsm_x4(ah[mi], aAh + addr);
            ldsm_x4(al[mi], aAl + addr);
        }
#pragma unroll
        for (int ni = 0; ni < 2; ni++) {
            uint32_t nb = (wn * 32 + ni * 16) * 2 + b_nc;
            uint32_t addr = swB(k0 + b_k, nb);
            ldsm_x4_t(bh[ni], aBh + addr);
            ldsm_x4_t(bl[ni], aBl + addr);
        }
#pragma unroll
        for (int mi = 0; mi < 4; mi++)
#pragma unroll
            for (int nj = 0; nj < 4; nj++) {
                int ni = nj >> 1, p = (nj & 1) * 2;
                mma_bf16(acc[mi][nj], ah[mi], bh[ni][p], bh[ni][p + 1]);
                mma_bf16(acc[mi][nj], ah[mi], bl[ni][p], bl[ni][p + 1]);
                mma_bf16(acc[mi][nj], al[mi], bh[ni][p], bh[ni][p + 1]);
            }
    }
}

// ---------------- GEMM1: H = gelu(X @ W1[e]) ---------------------------------
__global__ void __launch_bounds__(256, 1) ffn1_kernel(const float* __restrict__ x,
                                                      const float* __restrict__ w1) {
    int mt = blockIdx.x, nt = blockIdx.y;
    int e = g_tile_expert[mt];
    if (e < 0) return;

    extern __shared__ char smem[];
    uint32_t sbase = smem_u32(smem);
    int tid = threadIdx.x;
    int wid = tid >> 5, lane = tid & 31;
    int wm = wid >> 2, wn = wid & 3;
    int rbase = mt * TILE_M;

    // A loader: 16 lanes per row, rows j*16 + (tid>>4)
    int ar = tid >> 4;
    int ac = (tid & 15) * 4;
    const float* aptr[8];
#pragma unroll
    for (int j = 0; j < 8; j++) {
        int tok = g_row_token[rbase + j * 16 + ar];
        aptr[j] = (tok >= 0) ? (x + (size_t)tok * HID + ac) : nullptr;
    }
    // B loader: bk = tid>>2 row, n = (tid&3)*4 + j*16
    int bk = tid >> 2;
    int bn = (tid & 3) * 4;
    const float* bptr = w1 + (size_t)e * HID * FFN + nt * TILE_N + bn;

    float acc[4][4][4];
#pragma unroll
    for (int mi = 0; mi < 4; mi++)
#pragma unroll
        for (int nj = 0; nj < 4; nj++)
#pragma unroll
            for (int q = 0; q < 4; q++) acc[mi][nj][q] = 0.f;

    const int NC = HID / TILE_K;  // 12
    float4 stA[8], stB[8];

    // prologue: load + STS chunk 0
#pragma unroll
    for (int j = 0; j < 8; j++)
        stA[j] = aptr[j] ? *(const float4*)(aptr[j]) : make_float4(0.f, 0.f, 0.f, 0.f);
#pragma unroll
    for (int j = 0; j < 8; j++)
        stB[j] = *(const float4*)(bptr + (size_t)bk * FFN + j * 16);
    {
        char* bb = smem;
#pragma unroll
        for (int j = 0; j < 8; j++) {
            uint32_t h0 = pack_hi2(stA[j].x, stA[j].y), h1 = pack_hi2(stA[j].z, stA[j].w);
            uint32_t l0 = pack_lo2(stA[j].x, stA[j].y, h0), l1 = pack_lo2(stA[j].z, stA[j].w, h1);
            uint32_t off = swA(j * 16 + ar, ac * 2);
            *(uint2*)(bb + OFF_AH + off) = make_uint2(h0, h1);
            *(uint2*)(bb + OFF_AL + off) = make_uint2(l0, l1);
        }
#pragma unroll
        for (int j = 0; j < 8; j++) {
            uint32_t h0 = pack_hi2(stB[j].x, stB[j].y), h1 = pack_hi2(stB[j].z, stB[j].w);
            uint32_t l0 = pack_lo2(stB[j].x, stB[j].y, h0), l1 = pack_lo2(stB[j].z, stB[j].w, h1);
            uint32_t off = swB(bk, (bn + j * 16) * 2);
            *(uint2*)(bb + OFF_BH + off) = make_uint2(h0, h1);
            *(uint2*)(bb + OFF_BL + off) = make_uint2(l0, l1);
        }
    }
    __syncthreads();

    for (int c = 0; c < NC; c++) {
        if (c + 1 < NC) {
#pragma unroll
            for (int j = 0; j < 8; j++)
                stA[j] = aptr[j] ? *(const float4*)(aptr[j] + (c + 1) * TILE_K)
                                 : make_float4(0.f, 0.f, 0.f, 0.f);
#pragma unroll
            for (int j = 0; j < 8; j++)
                stB[j] = *(const float4*)(bptr + (size_t)((c + 1) * TILE_K + bk) * FFN + j * 16);
        }
        compute_chunk(sbase + (c & 1) * BUF_STRIDE, wm, wn, lane, acc);
        if (c + 1 < NC) {
            char* bb = smem + ((c + 1) & 1) * BUF_STRIDE;
#pragma unroll
            for (int j = 0; j < 8; j++) {
                uint32_t h0 = pack_hi2(stA[j].x, stA[j].y), h1 = pack_hi2(stA[j].z, stA[j].w);
                uint32_t l0 = pack_lo2(stA[j].x, stA[j].y, h0), l1 = pack_lo2(stA[j].z, stA[j].w, h1);
                uint32_t off = swA(j * 16 + ar, ac * 2);
                *(uint2*)(bb + OFF_AH + off) = make_uint2(h0, h1);
                *(uint2*)(bb + OFF_AL + off) = make_uint2(l0, l1);
            }
#pragma unroll
            for (int j = 0; j < 8; j++) {
                uint32_t h0 = pack_hi2(stB[j].x, stB[j].y), h1 = pack_hi2(stB[j].z, stB[j].w);
                uint32_t l0 = pack_lo2(stB[j].x, stB[j].y, h0), l1 = pack_lo2(stB[j].z, stB[j].w, h1);
                uint32_t off = swB(bk, (bn + j * 16) * 2);
                *(uint2*)(bb + OFF_BH + off) = make_uint2(h0, h1);
                *(uint2*)(bb + OFF_BL + off) = make_uint2(l0, l1);
            }
        }
        __syncthreads();
    }

    // epilogue: gelu + split bf16 -> g_Hh/g_Hl
    int r0 = rbase + wm * 64 + (lane >> 2);
    int cbase = nt * TILE_N + wn * 32 + (lane & 3) * 2;
#pragma unroll
    for (int mi = 0; mi < 4; mi++) {
#pragma unroll
        for (int nj = 0; nj < 4; nj++) {
            int col = cbase + nj * 8;
#pragma unroll
            for (int h = 0; h < 2; h++) {
                int row = r0 + mi * 16 + h * 8;
                float v0 = gelu_ex(acc[mi][nj][2 * h]);
                float v1 = gelu_ex(acc[mi][nj][2 * h + 1]);
                uint32_t hb = pack_hi2(v0, v1);
                uint32_t lb = pack_lo2(v0, v1, hb);
                size_t idx = (size_t)row * FFN + col;
                *(uint32_t*)(g_Hh + idx) = hb;
                *(uint32_t*)(g_Hl + idx) = lb;
            }
        }
    }
}

// ---------------- GEMM2: Y = H @ W2[e] ---------------------------------------
__global__ void __launch_bounds__(256, 1) ffn2_kernel(const float* __restrict__ w2) {
    int mt = blockIdx.x, nt = blockIdx.y;
    int e = g_tile_expert[mt];
    if (e < 0) return;

    extern __shared__ char smem[];
    uint32_t sbase = smem_u32(smem);
    int tid = threadIdx.x;
    int wid = tid >> 5, lane = tid & 31;
    int wm = wid >> 2, wn = wid & 3;
    int rbase = mt * TILE_M;

    // A loader: bf16 copy. m = tid>>1, k half = (tid&1)*32
    int am = tid >> 1;
    int akq = (tid & 1) * 32;
    const __nv_bfloat16* ahp = g_Hh + (size_t)(rbase + am) * FFN + akq;
    const __nv_bfloat16* alp = g_Hl + (size_t)(rbase + am) * FFN + akq;
    // B loader
    int bk = tid >> 2;
    int bn = (tid & 3) * 4;
    const float* bptr = w2 + (size_t)e * FFN * HID + nt * TILE_N + bn;

    float acc[4][4][4];
#pragma unroll
    for (int mi = 0; mi < 4; mi++)
#pragma unroll
        for (int nj = 0; nj < 4; nj++)
#pragma unroll
            for (int q = 0; q < 4; q++) acc[mi][nj][q] = 0.f;

    const int NC = FFN / TILE_K;  // 48
    uint4 sAh[4], sAl[4];
    float4 stB[8];

    // prologue chunk 0
#pragma unroll
    for (int j = 0; j < 4; j++) {
        sAh[j] = *(const uint4*)(ahp + j * 8);
        sAl[j] = *(const uint4*)(alp + j * 8);
    }
#pragma unroll
    for (int j = 0; j < 8; j++)
        stB[j] = *(const float4*)(bptr + (size_t)bk * HID + j * 16);
    {
        char* bb = smem;
#pragma unroll
        for (int j = 0; j < 4; j++) {
            uint32_t off = swA(am, (akq + j * 8) * 2);
            *(uint4*)(bb + OFF_AH + off) = sAh[j];
            *(uint4*)(bb + OFF_AL + off) = sAl[j];
        }
#pragma unroll
        for (int j = 0; j < 8; j++) {
            uint32_t h0 = pack_hi2(stB[j].x, stB[j].y), h1 = pack_hi2(stB[j].z, stB[j].w);
            uint32_t l0 = pack_lo2(stB[j].x, stB[j].y, h0), l1 = pack_lo2(stB[j].z, stB[j].w, h1);
            uint32_t off = swB(bk, (bn + j * 16) * 2);
            *(uint2*)(bb + OFF_BH + off) = make_uint2(h0, h1);
            *(uint2*)(bb + OFF_BL + off) = make_uint2(l0, l1);
        }
    }
    __syncthreads();

    for (int c = 0; c < NC; c++) {
        if (c + 1 < NC) {
#pragma unroll
            for (int j = 0; j < 4; j++) {
                sAh[j] = *(const uint4*)(ahp + (c + 1) * TILE_K + j * 8);
                sAl[j] = *(const uint4*)(alp + (c + 1) * TILE_K + j * 8);
            }
#pragma unroll
            for (int j = 0; j < 8; j++)
                stB[j] = *(const float4*)(bptr + (size_t)((c + 1) * TILE_K + bk) * HID + j * 16);
        }
        compute_chunk(sbase + (c & 1) * BUF_STRIDE, wm, wn, lane, acc);
        if (c + 1 < NC) {
            char* bb = smem + ((c + 1) & 1) * BUF_STRIDE;
#pragma unroll
            for (int j = 0; j < 4; j++) {
                uint32_t off = swA(am, (akq + j * 8) * 2);
                *(uint4*)(bb + OFF_AH + off) = sAh[j];
                *(uint4*)(bb + OFF_AL + off) = sAl[j];
            }
#pragma unroll
            for (int j = 0; j < 8; j++) {
                uint32_t h0 = pack_hi2(stB[j].x, stB[j].y), h1 = pack_hi2(stB[j].z, stB[j].w);
                uint32_t l0 = pack_lo2(stB[j].x, stB[j].y, h0), l1 = pack_lo2(stB[j].z, stB[j].w, h1);
                uint32_t off = swB(bk, (bn + j * 16) * 2);
                *(uint2*)(bb + OFF_BH + off) = make_uint2(h0, h1);
                *(uint2*)(bb + OFF_BL + off) = make_uint2(l0, l1);
            }
        }
        __syncthreads();
    }

    // epilogue: fp32 -> g_Y
    int r0 = rbase + wm * 64 + (lane >> 2);
    int cbase = nt * TILE_N + wn * 32 + (lane & 3) * 2;
#pragma unroll
    for (int mi = 0; mi < 4; mi++) {
#pragma unroll
        for (int nj = 0; nj < 4; nj++) {
            int col = cbase + nj * 8;
#pragma unroll
            for (int h = 0; h < 2; h++) {
                int row = r0 + mi * 16 + h * 8;
                *(float2*)(g_Y + (size_t)row * HID + col) =
                    make_float2(acc[mi][nj][2 * h], acc[mi][nj][2 * h + 1]);
            }
        }
    }
}

// ---------------- combine ----------------------------------------------------
__global__ void combine_kernel(float* __restrict__ out) {
    int n = blockIdx.x;
    int h4 = threadIdx.x * 4;
    if (h4 >= HID) return;
    int   r0 = g_slot_row[2 * n],  r1 = g_slot_row[2 * n + 1];
    float g0 = g_slot_gate[2 * n], g1 = g_slot_gate[2 * n + 1];
    float4 a = *(const float4*)(g_Y + (size_t)r0 * HID + h4);
    float4 b = *(const float4*)(g_Y + (size_t)r1 * HID + h4);
    float4 o;
    o.x = g0 * a.x + g1 * b.x;
    o.y = g0 * a.y + g1 * b.y;
    o.z = g0 * a.z + g1 * b.z;
    o.w = g0 * a.w + g1 * b.w;
    *(float4*)(out + (size_t)n * HID + h4) = o;
}

// ---------------- launch -----------------------------------------------------
extern "C" void kernel_launch(void* const* d_in, const int* in_sizes, int n_in,
                              void* d_out, int out_size) {
    const float* x  = (const float*)d_in[0];
    const float* rw = (const float*)d_in[1];
    const float* w1 = (const float*)d_in[2];
    const float* w2 = (const float*)d_in[3];
    float* out = (float*)d_out;

    static int attr_done = 0;
    if (!attr_done) {
        cudaFuncSetAttribute(ffn1_kernel, cudaFuncAttributeMaxDynamicSharedMemorySize, SMEM_BYTES);
        cudaFuncSetAttribute(ffn2_kernel, cudaFuncAttributeMaxDynamicSharedMemorySize, SMEM_BYTES);
        attr_done = 1;
    }

    init_kernel<<<(MAXROWS + 255) / 256, 256>>>();
    router_kernel<<<(NTOK * 32 + 255) / 256, 256>>>(x, rw);
    scan_kernel<<<1, 32>>>();
    scatter_kernel<<<(SLOTS + 255) / 256, 256>>>();
    ffn1_kernel<<<dim3(MAX_MT, NT1), 256, SMEM_BYTES>>>(x, w1);
    ffn2_kernel<<<dim3(MAX_MT, NT2), 256, SMEM_BYTES>>>(w2);
    combine_kernel<<<NTOK, HID / 4>>>(out);
}